// round 15
// baseline (speedup 1.0000x reference)
#include <cuda_runtime.h>

#define DIM 128
#define N 512
#define HEADS 4
#define DH 32
#define HID 128
#define IND 5
#define ATTN_SCALE 0.17677669529663687f   // 32^-0.5

// Scratch (allocation-free rule: __device__ globals). 256B-aligned (vector access).
__device__ __align__(256) float g_qkv[3 * HID * N];     // [384][512] q|k|v
__device__ __align__(256) float g_A2[HEADS * IND * N];  // [h][c][i]
__device__ __align__(256) float g_B3[HEADS * IND * N];  // [h][c][j]
__device__ __align__(256) float g_W4[HEADS * 25];       // [h][c*5+cp]

// ---------------------------------------------------------------------------
// K1: qkv = w_qkv (384x128) @ x (128x512). TM=32, TN=32, TK=16, 256 threads,
// grid (16,12)=192 blocks. Register double-buffer; epilogue computes A2/B3/W4.
// ---------------------------------------------------------------------------
__global__ __launch_bounds__(256) void k_qkv(const float* __restrict__ A,
                                             const float* __restrict__ B,
                                             const float* __restrict__ w_ind,
                                             float* __restrict__ C) {
    __shared__ float As[16][32];
    __shared__ float Bs[16][32];
    __shared__ float Cs[32][33];
    __shared__ float wsm[32][5];
    const int n0 = blockIdx.x * 32;
    const int m0 = blockIdx.y * 32;
    const int t  = threadIdx.x;
    const int tx = t & 15, ty = t >> 4;

    const int a_k = t & 15, a_m = t >> 4;
    const int b_n = t & 31, b_k = t >> 5;

    As[a_k][a_m]      = A[(m0 + a_m) * DIM + a_k];
    As[a_k][a_m + 16] = A[(m0 + a_m + 16) * DIM + a_k];
    Bs[b_k][b_n]      = B[b_k * N + n0 + b_n];
    Bs[b_k + 8][b_n]  = B[(b_k + 8) * N + n0 + b_n];
    __syncthreads();

    float acc[2][2] = {};
    for (int k0 = 0; k0 < DIM; k0 += 16) {
        float ra0 = 0.f, ra1 = 0.f, rb0 = 0.f, rb1 = 0.f;
        const bool more = (k0 + 16 < DIM);
        if (more) {
            ra0 = A[(m0 + a_m) * DIM + k0 + 16 + a_k];
            ra1 = A[(m0 + a_m + 16) * DIM + k0 + 16 + a_k];
            rb0 = B[(k0 + 16 + b_k) * N + n0 + b_n];
            rb1 = B[(k0 + 24 + b_k) * N + n0 + b_n];
        }
#pragma unroll
        for (int kk = 0; kk < 16; kk++) {
            float2 a = ((const float2*)&As[kk][0])[ty];
            float2 b = ((const float2*)&Bs[kk][0])[tx];
            acc[0][0] = fmaf(a.x, b.x, acc[0][0]);
            acc[0][1] = fmaf(a.x, b.y, acc[0][1]);
            acc[1][0] = fmaf(a.y, b.x, acc[1][0]);
            acc[1][1] = fmaf(a.y, b.y, acc[1][1]);
        }
        __syncthreads();
        if (more) {
            As[a_k][a_m]      = ra0;
            As[a_k][a_m + 16] = ra1;
            Bs[b_k][b_n]      = rb0;
            Bs[b_k + 8][b_n]  = rb1;
            __syncthreads();
        }
    }
#pragma unroll
    for (int r = 0; r < 2; r++) {
        int m = ty * 2 + r;
        float* cp = &C[(m0 + m) * N + n0 + tx * 2];
        cp[0] = acc[r][0]; cp[1] = acc[r][1];
        Cs[m][tx * 2 + 0] = acc[r][0];
        Cs[m][tx * 2 + 1] = acc[r][1];
    }

    if (m0 < 2 * HID) {
        const bool isQ = (m0 < HID);
        const int wbase = isQ ? (HID + m0) : (m0 - HID);
        if (t < 160) wsm[t / 5][t % 5] = w_ind[(wbase + t / 5) * IND + (t % 5)];
        __syncthreads();
        const int h = (isQ ? m0 : m0 - HID) >> 5;
        float* dst = (isQ ? g_A2 : g_B3);
        if (t < 160) {
            int col = t & 31, c = t >> 5;
            float s = 0.f;
#pragma unroll
            for (int d = 0; d < DH; d++)
                s = fmaf(Cs[d][col], wsm[d][c], s);
            dst[(h * IND + c) * N + n0 + col] = s;
        }
    } else if (m0 == 2 * HID && n0 == 0) {
        if (t < HEADS * 25) {
            int h = t / 25, c = (t % 25) / 5, cp = t % 5;
            float s = 0.f;
#pragma unroll
            for (int d = 0; d < DH; d++)
                s = fmaf(w_ind[(h * DH + d) * IND + c],
                         w_ind[(HID + h * DH + d) * IND + cp], s);
            g_W4[t] = s;
        }
    }
}

// ---------------------------------------------------------------------------
// K2: fully fused qk + sim + softmax + attn@v + w_out projection.
// FOUR i's per block, 1024 threads (grid 128, 32 warps/SM).
// Pass A: two 512-thread groups each own 2 i's (halved register state).
// Softmax: 2 warps per (ii,h). av/proj: 4 rows per warp.
// ---------------------------------------------------------------------------
__global__ __launch_bounds__(1024, 1) void k_fused(const float* __restrict__ indicator,
                                                   const float* __restrict__ w_out,
                                                   const float* __restrict__ b_out,
                                                   float* __restrict__ out) {
    const int i0 = blockIdx.x * 4;      // handles i0..i0+3
    const int t = threadIdx.x;          // 0..1023
    const int warp = t >> 5, lane = t & 31;
    const int j   = t & 511;            // Pass A column
    const int iig = t >> 9;             // 0: ii 0-1, 1: ii 2-3

    __shared__ float a2s[4][HEADS][IND];
    __shared__ float w4s[HEADS][25];
    __shared__ float red_m[16][2];
    __shared__ float red_s[16][2];
    __shared__ float inv_s[4][HEADS];
    __shared__ __align__(16) float qsm[HEADS][DH][4];  // q[h][d][ii], 2 KB
    __shared__ __align__(16) float ps[4][HEADS][N];    // 32 KB: sims -> probs
    __shared__ __align__(16) float avs[4][HID];        // 2 KB

    // q-slice: threads 0..511 -> (h, d, ii)
    if (t < 512) {
        int h = t >> 7, rem = t & 127, d = rem >> 2, ii = rem & 3;
        qsm[h][d][ii] = g_qkv[(h * DH + d) * N + i0 + ii];
    } else if (t < 512 + 80) {
        int u = t - 512;
        int ii = u / 20, v = u % 20;
        a2s[ii][v / 5][v % 5] = g_A2[v * N + i0 + ii];
    } else if (t < 512 + 180) {
        int u = t - 512 - 80;
        w4s[u / 25][u % 25] = g_W4[u];
    }
    __syncthreads();

    // ---- qk on the fly: qk[ii2][h] = sum_d q[h,d,i0+iig*2+ii2] * k[h,d,j] ----
    float qk[2][HEADS] = {};
#pragma unroll
    for (int h = 0; h < HEADS; h++) {
#pragma unroll
        for (int d = 0; d < DH; d++) {
            float kv = g_qkv[(HID + h * DH + d) * N + j];
            float2 qv = *(const float2*)&qsm[h][d][iig * 2];
            qk[0][h] = fmaf(qv.x, kv, qk[0][h]);
            qk[1][h] = fmaf(qv.y, kv, qk[1][h]);
        }
    }

    // ---- Pass A: raw sims into smem (2 i's per thread) ----
    {
        float iv[2][IND];
#pragma unroll
        for (int ii2 = 0; ii2 < 2; ii2++)
#pragma unroll
            for (int c = 0; c < IND; c++)
                iv[ii2][c] = indicator[((size_t)c * N + i0 + iig * 2 + ii2) * N + j];

#pragma unroll
        for (int h = 0; h < HEADS; h++) {
            float b3[IND];
#pragma unroll
            for (int c = 0; c < IND; c++)
                b3[c] = g_B3[(h * IND + c) * N + j];
#pragma unroll
            for (int ii2 = 0; ii2 < 2; ii2++) {
                float lin = 0.f, quad = 0.f;
#pragma unroll
                for (int c = 0; c < IND; c++) {
                    lin = fmaf(iv[ii2][c], a2s[iig * 2 + ii2][h][c] + b3[c], lin);
                    float tt = 0.f;
#pragma unroll
                    for (int cp = 0; cp < IND; cp++)
                        tt = fmaf(w4s[h][c * 5 + cp], iv[ii2][cp], tt);
                    quad = fmaf(iv[ii2][c], tt, quad);
                }
                ps[iig * 2 + ii2][h][j] = ATTN_SCALE * (qk[ii2][h] + lin + quad);
            }
        }
    }
    __syncthreads();

    // ---- softmax: 2 warps per (ii,h) pair, each owns 256 elements ----
    {
        const int p = warp >> 1;            // 0..15 -> (ii, h)
        const int half = warp & 1;
        const int ii = p >> 2, h = p & 3;
        float4* pr = (float4*)&ps[ii][h][half * 256];   // 64 float4
        float4 v0 = pr[lane], v1 = pr[lane + 32];
        float m = fmaxf(fmaxf(fmaxf(v0.x, v0.y), fmaxf(v0.z, v0.w)),
                        fmaxf(fmaxf(v1.x, v1.y), fmaxf(v1.z, v1.w)));
#pragma unroll
        for (int off = 16; off; off >>= 1)
            m = fmaxf(m, __shfl_xor_sync(0xffffffffu, m, off));
        if (lane == 0) red_m[p][half] = m;
        __syncthreads();
        float gmax = fmaxf(red_m[p][0], red_m[p][1]);

        v0.x = __expf(v0.x - gmax); v0.y = __expf(v0.y - gmax);
        v0.z = __expf(v0.z - gmax); v0.w = __expf(v0.w - gmax);
        v1.x = __expf(v1.x - gmax); v1.y = __expf(v1.y - gmax);
        v1.z = __expf(v1.z - gmax); v1.w = __expf(v1.w - gmax);
        pr[lane] = v0; pr[lane + 32] = v1;
        float s = (v0.x + v0.y) + (v0.z + v0.w) + (v1.x + v1.y) + (v1.z + v1.w);
#pragma unroll
        for (int off = 16; off; off >>= 1)
            s += __shfl_xor_sync(0xffffffffu, s, off);
        if (lane == 0) red_s[p][half] = s;
        __syncthreads();
        if (half == 0 && lane == 0)
            inv_s[ii][h] = 1.0f / (red_s[p][0] + red_s[p][1]);
    }
    __syncthreads();

    // ---- attn@v: 128 rows / 32 warps = 4 rows per warp ----
#pragma unroll
    for (int rr = 0; rr < 4; rr++) {
        int row = warp * 4 + rr;             // 0..127
        int h = row >> 5;
        const float4* vr = (const float4*)(g_qkv + (2 * HID + row) * N);
        float acc[4] = {};
#pragma unroll
        for (int k2 = 0; k2 < 4; k2++) {
            float4 v4 = vr[lane + 32 * k2];
#pragma unroll
            for (int ii = 0; ii < 4; ii++) {
                float4 p4 = ((const float4*)&ps[ii][h][0])[lane + 32 * k2];
                acc[ii] = fmaf(v4.x, p4.x, acc[ii]);
                acc[ii] = fmaf(v4.y, p4.y, acc[ii]);
                acc[ii] = fmaf(v4.z, p4.z, acc[ii]);
                acc[ii] = fmaf(v4.w, p4.w, acc[ii]);
            }
        }
#pragma unroll
        for (int off = 16; off; off >>= 1)
#pragma unroll
            for (int ii = 0; ii < 4; ii++)
                acc[ii] += __shfl_xor_sync(0xffffffffu, acc[ii], off);
        if (lane == 0)
#pragma unroll
            for (int ii = 0; ii < 4; ii++)
                avs[ii][row] = acc[ii] * inv_s[ii][h];
    }
    __syncthreads();

    // ---- projection: 128 o rows / 32 warps = 4 per warp ----
#pragma unroll
    for (int rr = 0; rr < 4; rr++) {
        int o = warp * 4 + rr;               // 0..127
        float4 w4 = ((const float4*)(w_out + o * HID))[lane];
        float acc[4];
#pragma unroll
        for (int ii = 0; ii < 4; ii++) {
            float4 a4 = ((const float4*)&avs[ii][0])[lane];
            acc[ii] = w4.x * a4.x + w4.y * a4.y + w4.z * a4.z + w4.w * a4.w;
        }
#pragma unroll
        for (int off = 16; off; off >>= 1)
#pragma unroll
            for (int ii = 0; ii < 4; ii++)
                acc[ii] += __shfl_xor_sync(0xffffffffu, acc[ii], off);
        if (lane == 0) {
            float bv = b_out[o];
#pragma unroll
            for (int ii = 0; ii < 4; ii++)
                out[o * N + i0 + ii] = acc[ii] + bv;
        }
    }
}

// ---------------------------------------------------------------------------
extern "C" void kernel_launch(void* const* d_in, const int* in_sizes, int n_in,
                              void* d_out, int out_size) {
    const float* x         = (const float*)d_in[0];   // (1,128,512)
    const float* indicator = (const float*)d_in[1];   // (1,5,512,512)
    const float* w_qkv     = (const float*)d_in[2];   // (384,128)
    const float* w_ind     = (const float*)d_in[3];   // (256,5)
    const float* w_out     = (const float*)d_in[4];   // (128,128)
    const float* b_out     = (const float*)d_in[5];   // (128,)
    float* out             = (float*)d_out;           // (1,128,512)

    float* qkv;  cudaGetSymbolAddress((void**)&qkv, g_qkv);

    k_qkv<<<dim3(16, 12), 256>>>(w_qkv, x, w_ind, qkv);    // qkv + A2/B3/W4
    k_fused<<<N / 4, 1024>>>(indicator, w_out, b_out, out); // qk+sim+softmax+av+proj
}

// round 16
// speedup vs baseline: 1.1509x; 1.1509x over previous
#include <cuda_runtime.h>

#define DIM 128
#define N 512
#define HEADS 4
#define DH 32
#define HID 128
#define IND 5
#define ATTN_SCALE 0.17677669529663687f   // 32^-0.5

// Scratch (allocation-free rule: __device__ globals). 256B-aligned (vector access).
__device__ __align__(256) float g_qkv[3 * HID * N];     // [384][512] q|k|v
__device__ __align__(256) float g_A2[HEADS * IND * N];  // [h][c][i]
__device__ __align__(256) float g_B3[HEADS * IND * N];  // [h][c][j]
__device__ __align__(256) float g_W4[HEADS * 25];       // [h][c*5+cp]

// ---------------------------------------------------------------------------
// K1: qkv = w_qkv (384x128) @ x (128x512). TM=32, TN=32, TK=16, 256 threads,
// grid (16,12)=192 blocks. Register double-buffer; epilogue computes A2/B3/W4.
// ---------------------------------------------------------------------------
__global__ __launch_bounds__(256) void k_qkv(const float* __restrict__ A,
                                             const float* __restrict__ B,
                                             const float* __restrict__ w_ind,
                                             float* __restrict__ C) {
    __shared__ float As[16][32];
    __shared__ float Bs[16][32];
    __shared__ float Cs[32][33];
    __shared__ float wsm[32][5];
    const int n0 = blockIdx.x * 32;
    const int m0 = blockIdx.y * 32;
    const int t  = threadIdx.x;
    const int tx = t & 15, ty = t >> 4;

    const int a_k = t & 15, a_m = t >> 4;
    const int b_n = t & 31, b_k = t >> 5;

    As[a_k][a_m]      = A[(m0 + a_m) * DIM + a_k];
    As[a_k][a_m + 16] = A[(m0 + a_m + 16) * DIM + a_k];
    Bs[b_k][b_n]      = B[b_k * N + n0 + b_n];
    Bs[b_k + 8][b_n]  = B[(b_k + 8) * N + n0 + b_n];
    __syncthreads();

    float acc[2][2] = {};
    for (int k0 = 0; k0 < DIM; k0 += 16) {
        float ra0 = 0.f, ra1 = 0.f, rb0 = 0.f, rb1 = 0.f;
        const bool more = (k0 + 16 < DIM);
        if (more) {
            ra0 = A[(m0 + a_m) * DIM + k0 + 16 + a_k];
            ra1 = A[(m0 + a_m + 16) * DIM + k0 + 16 + a_k];
            rb0 = B[(k0 + 16 + b_k) * N + n0 + b_n];
            rb1 = B[(k0 + 24 + b_k) * N + n0 + b_n];
        }
#pragma unroll
        for (int kk = 0; kk < 16; kk++) {
            float2 a = ((const float2*)&As[kk][0])[ty];
            float2 b = ((const float2*)&Bs[kk][0])[tx];
            acc[0][0] = fmaf(a.x, b.x, acc[0][0]);
            acc[0][1] = fmaf(a.x, b.y, acc[0][1]);
            acc[1][0] = fmaf(a.y, b.x, acc[1][0]);
            acc[1][1] = fmaf(a.y, b.y, acc[1][1]);
        }
        __syncthreads();
        if (more) {
            As[a_k][a_m]      = ra0;
            As[a_k][a_m + 16] = ra1;
            Bs[b_k][b_n]      = rb0;
            Bs[b_k + 8][b_n]  = rb1;
            __syncthreads();
        }
    }
#pragma unroll
    for (int r = 0; r < 2; r++) {
        int m = ty * 2 + r;
        float* cp = &C[(m0 + m) * N + n0 + tx * 2];
        cp[0] = acc[r][0]; cp[1] = acc[r][1];
        Cs[m][tx * 2 + 0] = acc[r][0];
        Cs[m][tx * 2 + 1] = acc[r][1];
    }

    if (m0 < 2 * HID) {
        const bool isQ = (m0 < HID);
        const int wbase = isQ ? (HID + m0) : (m0 - HID);
        if (t < 160) wsm[t / 5][t % 5] = w_ind[(wbase + t / 5) * IND + (t % 5)];
        __syncthreads();
        const int h = (isQ ? m0 : m0 - HID) >> 5;
        float* dst = (isQ ? g_A2 : g_B3);
        if (t < 160) {
            int col = t & 31, c = t >> 5;
            float s = 0.f;
#pragma unroll
            for (int d = 0; d < DH; d++)
                s = fmaf(Cs[d][col], wsm[d][c], s);
            dst[(h * IND + c) * N + n0 + col] = s;
        }
    } else if (m0 == 2 * HID && n0 == 0) {
        if (t < HEADS * 25) {
            int h = t / 25, c = (t % 25) / 5, cp = t % 5;
            float s = 0.f;
#pragma unroll
            for (int d = 0; d < DH; d++)
                s = fmaf(w_ind[(h * DH + d) * IND + c],
                         w_ind[(HID + h * DH + d) * IND + cp], s);
            g_W4[t] = s;
        }
    }
}

// ---------------------------------------------------------------------------
// K2: fully fused qk + sim + softmax + attn@v + w_out projection.
// FOUR i's per block, 512 threads (grid 128). R14 champion base; av and proj
// phases restructured to amortize ps/avs smem reads across rows (4x LDS cut).
// ---------------------------------------------------------------------------
__global__ __launch_bounds__(512) void k_fused(const float* __restrict__ indicator,
                                               const float* __restrict__ w_out,
                                               const float* __restrict__ b_out,
                                               float* __restrict__ out) {
    const int i0 = blockIdx.x * 4;      // handles i0..i0+3
    const int t = threadIdx.x;          // Pass A: owns column j = t
    const int warp = t >> 5, lane = t & 31;

    __shared__ float a2s[4][HEADS][IND];
    __shared__ float w4s[HEADS][25];
    __shared__ float inv_s[4][HEADS];
    __shared__ __align__(16) float qsm[HEADS][DH][4];  // q[h][d][ii], 2 KB
    __shared__ __align__(16) float ps[4][HEADS][N];    // 32 KB: sims -> probs
    __shared__ __align__(16) float avs[4][HID];        // 2 KB

    // q-slice: thread t -> (h, d, ii)
    {
        int h = t >> 7, rem = t & 127, d = rem >> 2, ii = rem & 3;
        qsm[h][d][ii] = g_qkv[(h * DH + d) * N + i0 + ii];
    }
    if (t < 80) {
        int ii = t / 20, u = t % 20;
        a2s[ii][u / 5][u % 5] = g_A2[u * N + i0 + ii];
    } else if (t < 180) {
        int u = t - 80;
        w4s[u / 25][u % 25] = g_W4[u];
    }
    __syncthreads();

    // ---- qk on the fly: qk[ii][h] = sum_d q[h,d,i0+ii] * k[h,d,t] ----
    float qk[4][HEADS] = {};
#pragma unroll
    for (int h = 0; h < HEADS; h++) {
#pragma unroll
        for (int d = 0; d < DH; d++) {
            float kv = g_qkv[(HID + h * DH + d) * N + t];
            float4 qv = *(const float4*)&qsm[h][d][0];
            qk[0][h] = fmaf(qv.x, kv, qk[0][h]);
            qk[1][h] = fmaf(qv.y, kv, qk[1][h]);
            qk[2][h] = fmaf(qv.z, kv, qk[2][h]);
            qk[3][h] = fmaf(qv.w, kv, qk[3][h]);
        }
    }

    // ---- Pass A: raw sims into smem ----
#pragma unroll
    for (int ii = 0; ii < 4; ii++) {
        float iv[IND];
#pragma unroll
        for (int c = 0; c < IND; c++)
            iv[c] = indicator[((size_t)c * N + i0 + ii) * N + t];
#pragma unroll
        for (int h = 0; h < HEADS; h++) {
            float lin = 0.f, quad = 0.f;
#pragma unroll
            for (int c = 0; c < IND; c++) {
                float b3 = g_B3[(h * IND + c) * N + t];
                lin = fmaf(iv[c], a2s[ii][h][c] + b3, lin);
                float tt = 0.f;
#pragma unroll
                for (int cp = 0; cp < IND; cp++)
                    tt = fmaf(w4s[h][c * 5 + cp], iv[cp], tt);
                quad = fmaf(iv[c], tt, quad);
            }
            ps[ii][h][t] = ATTN_SCALE * (qk[ii][h] + lin + quad);
        }
    }
    __syncthreads();

    // ---- softmax: one warp per (ii,h) pair over its 512 sims ----
    {
        const int ii = warp >> 2, h = warp & 3;
        float4* pr = (float4*)&ps[ii][h][0];
        float4 vals[4];
        float m = -1e30f;
#pragma unroll
        for (int k2 = 0; k2 < 4; k2++) {
            vals[k2] = pr[lane + 32 * k2];
            m = fmaxf(m, fmaxf(fmaxf(vals[k2].x, vals[k2].y),
                               fmaxf(vals[k2].z, vals[k2].w)));
        }
#pragma unroll
        for (int off = 16; off; off >>= 1)
            m = fmaxf(m, __shfl_xor_sync(0xffffffffu, m, off));
        float s = 0.f;
#pragma unroll
        for (int k2 = 0; k2 < 4; k2++) {
            vals[k2].x = __expf(vals[k2].x - m);
            vals[k2].y = __expf(vals[k2].y - m);
            vals[k2].z = __expf(vals[k2].z - m);
            vals[k2].w = __expf(vals[k2].w - m);
            s += (vals[k2].x + vals[k2].y) + (vals[k2].z + vals[k2].w);
            pr[lane + 32 * k2] = vals[k2];
        }
#pragma unroll
        for (int off = 16; off; off >>= 1)
            s += __shfl_xor_sync(0xffffffffu, s, off);
        if (lane == 0) inv_s[ii][h] = 1.0f / s;
    }
    __syncthreads();

    // ---- attn@v: warp owns 8 rows (all same h); process in 4-row chunks so
    // each ps read is reused across 4 v-rows (4x LDS reduction) ----
    {
        const int h = (warp * 8) >> 5;
#pragma unroll
        for (int chunk = 0; chunk < 2; chunk++) {
            const int row0 = warp * 8 + chunk * 4;
            float acc[4][4] = {};                 // [rr][ii]
#pragma unroll
            for (int k2 = 0; k2 < 4; k2++) {
                float4 v4[4];
#pragma unroll
                for (int rr = 0; rr < 4; rr++)
                    v4[rr] = ((const float4*)(g_qkv + (2 * HID + row0 + rr) * N))[lane + 32 * k2];
#pragma unroll
                for (int ii = 0; ii < 4; ii++) {
                    float4 p4 = ((const float4*)&ps[ii][h][0])[lane + 32 * k2];
#pragma unroll
                    for (int rr = 0; rr < 4; rr++) {
                        acc[rr][ii] = fmaf(v4[rr].x, p4.x, acc[rr][ii]);
                        acc[rr][ii] = fmaf(v4[rr].y, p4.y, acc[rr][ii]);
                        acc[rr][ii] = fmaf(v4[rr].z, p4.z, acc[rr][ii]);
                        acc[rr][ii] = fmaf(v4[rr].w, p4.w, acc[rr][ii]);
                    }
                }
            }
#pragma unroll
            for (int off = 16; off; off >>= 1)
#pragma unroll
                for (int rr = 0; rr < 4; rr++)
#pragma unroll
                    for (int ii = 0; ii < 4; ii++)
                        acc[rr][ii] += __shfl_xor_sync(0xffffffffu, acc[rr][ii], off);
            if (lane == 0)
#pragma unroll
                for (int rr = 0; rr < 4; rr++)
#pragma unroll
                    for (int ii = 0; ii < 4; ii++)
                        avs[ii][row0 + rr] = acc[rr][ii] * inv_s[ii][h];
        }
    }
    __syncthreads();

    // ---- projection: avs loaded once per warp, reused across 8 o-rows ----
    {
        float4 a4[4];
#pragma unroll
        for (int ii = 0; ii < 4; ii++)
            a4[ii] = ((const float4*)&avs[ii][0])[lane];
#pragma unroll
        for (int rr = 0; rr < 8; rr++) {
            int o = warp * 8 + rr;               // 0..127
            float4 w4 = ((const float4*)(w_out + o * HID))[lane];
            float acc[4];
#pragma unroll
            for (int ii = 0; ii < 4; ii++)
                acc[ii] = w4.x * a4[ii].x + w4.y * a4[ii].y
                        + w4.z * a4[ii].z + w4.w * a4[ii].w;
#pragma unroll
            for (int off = 16; off; off >>= 1)
#pragma unroll
                for (int ii = 0; ii < 4; ii++)
                    acc[ii] += __shfl_xor_sync(0xffffffffu, acc[ii], off);
            if (lane == 0) {
                float bv = b_out[o];
#pragma unroll
                for (int ii = 0; ii < 4; ii++)
                    out[o * N + i0 + ii] = acc[ii] + bv;
            }
        }
    }
}

// ---------------------------------------------------------------------------
extern "C" void kernel_launch(void* const* d_in, const int* in_sizes, int n_in,
                              void* d_out, int out_size) {
    const float* x         = (const float*)d_in[0];   // (1,128,512)
    const float* indicator = (const float*)d_in[1];   // (1,5,512,512)
    const float* w_qkv     = (const float*)d_in[2];   // (384,128)
    const float* w_ind     = (const float*)d_in[3];   // (256,5)
    const float* w_out     = (const float*)d_in[4];   // (128,128)
    const float* b_out     = (const float*)d_in[5];   // (128,)
    float* out             = (float*)d_out;           // (1,128,512)

    float* qkv;  cudaGetSymbolAddress((void**)&qkv, g_qkv);

    k_qkv<<<dim3(16, 12), 256>>>(w_qkv, x, w_ind, qkv);    // qkv + A2/B3/W4
    k_fused<<<N / 4, 512>>>(indicator, w_out, b_out, out);  // qk+sim+softmax+av+proj
}